// round 2
// baseline (speedup 1.0000x reference)
#include <cuda_runtime.h>

// Problem constants
#define Bb 16
#define Nn 2048
#define Dd 128
#define MASKN 2049
#define MROWS (Bb * Nn)

#define NEGINF __int_as_float(0xff800000)

// Scratch (allocation-free rule: __device__ globals)
__device__ float g_q[MROWS * Dd];
__device__ float g_k[MROWS * Dd];
__device__ float g_v[MROWS * Dd];
__device__ float g_ao[MROWS * Dd];

// ---------------------------------------------------------------------------
// Projection: Y[M,128] = X[M,128] @ W[128,128] + bias
// CTA: 64 rows, 256 threads. X tile in smem; W streamed through L1 (__ldg).
// ---------------------------------------------------------------------------
__global__ __launch_bounds__(256) void proj_kernel(
    const float* __restrict__ X, const float* __restrict__ W,
    const float* __restrict__ bias, float* __restrict__ Y) {
    __shared__ float Xs[64 * 128];
    const int tid = threadIdx.x;
    const size_t row0 = (size_t)blockIdx.x * 64;

    const float4* Xg = (const float4*)(X + row0 * Dd);
    float4* Xs4 = (float4*)Xs;
#pragma unroll
    for (int i = 0; i < 8; i++) Xs4[tid + i * 256] = Xg[tid + i * 256];
    __syncthreads();

    const int ty = tid >> 4, tx = tid & 15;
    const float4* W4 = (const float4*)W;

    float acc[4][8];
#pragma unroll
    for (int i = 0; i < 4; i++)
#pragma unroll
        for (int j = 0; j < 8; j++) acc[i][j] = 0.0f;

#pragma unroll 4
    for (int kk = 0; kk < 128; kk++) {
        float4 w0 = __ldg(&W4[kk * 32 + tx]);
        float4 w1 = __ldg(&W4[kk * 32 + tx + 16]);
#pragma unroll
        for (int i = 0; i < 4; i++) {
            float xv = Xs[(4 * ty + i) * 128 + kk];
            acc[i][0] += xv * w0.x; acc[i][1] += xv * w0.y;
            acc[i][2] += xv * w0.z; acc[i][3] += xv * w0.w;
            acc[i][4] += xv * w1.x; acc[i][5] += xv * w1.y;
            acc[i][6] += xv * w1.z; acc[i][7] += xv * w1.w;
        }
    }

    float4 b0 = __ldg(&((const float4*)bias)[tx]);
    float4 b1 = __ldg(&((const float4*)bias)[tx + 16]);
#pragma unroll
    for (int i = 0; i < 4; i++) {
        float4 o0 = make_float4(acc[i][0] + b0.x, acc[i][1] + b0.y,
                                acc[i][2] + b0.z, acc[i][3] + b0.w);
        float4 o1 = make_float4(acc[i][4] + b1.x, acc[i][5] + b1.y,
                                acc[i][6] + b1.z, acc[i][7] + b1.w);
        float4* yr = (float4*)(Y + (row0 + 4 * ty + i) * Dd);
        yr[tx] = o0;
        yr[tx + 16] = o1;
    }
}

// ---------------------------------------------------------------------------
// Flash attention: per CTA, BM=64 query rows of one batch; loop BN=64 keys.
// 512 threads. Online softmax with m/l running stats; fully-masked rows -> 0.
// mask[b, 1+q, 1+k] != 0  =>  score = -inf.  Mask stored as int32 on device.
// ---------------------------------------------------------------------------
#define BM 64
#define BN 64
#define KP 132   // Ks row pad: stride-4-row float4 loads hit 2 phases
#define SP 65    // Ss row pad: conflict-free column scans in softmax

#define ATTN_SMEM_FLOATS (64*128 + 64*KP + 64*128 + 64*SP + 64*3 + 8*64)

__global__ __launch_bounds__(512, 1) void attn_kernel(
    const float* __restrict__ q, const float* __restrict__ k,
    const float* __restrict__ v, const int* __restrict__ mask,
    float* __restrict__ out) {
    extern __shared__ float sm[];
    float* Qs = sm;                       // 64 x 128 (pre-scaled)
    float* Ks = Qs + 64 * 128;            // 64 x KP
    float* Vs = Ks + 64 * KP;             // 64 x 128
    float* Ss = Vs + 64 * 128;            // 64 x SP
    float* m_s = Ss + 64 * SP;            // 64
    float* l_s = m_s + 64;                // 64
    float* corr_s = l_s + 64;             // 64
    float* red = corr_s + 64;             // 8 x 64

    const int tid = threadIdx.x;
    const int b = blockIdx.y;
    const int q0 = blockIdx.x * BM;
    const float SCALE = 0.08838834764831845f;  // 1/sqrt(128)

    // Load Q tile, pre-scaled
    const float4* Qg = (const float4*)(q + ((size_t)b * Nn + q0) * Dd);
    float4* Qs4 = (float4*)Qs;
#pragma unroll
    for (int i = 0; i < 4; i++) {
        float4 t = Qg[tid + i * 512];
        t.x *= SCALE; t.y *= SCALE; t.z *= SCALE; t.w *= SCALE;
        Qs4[tid + i * 512] = t;
    }
    if (tid < 64) { m_s[tid] = NEGINF; l_s[tid] = 0.0f; }

    const int sy = tid >> 4, sx = tid & 15;  // score: rows {2sy,2sy+1}, cols sx+16j
    const int vy = sy, vx = sx;              // PV: rows {2vy,2vy+1}, cols 4vx+j & 64+4vx+j

    float acc[2][8];
#pragma unroll
    for (int i = 0; i < 2; i++)
#pragma unroll
        for (int j = 0; j < 8; j++) acc[i][j] = 0.0f;

    const int* mb =
        mask + (size_t)b * MASKN * MASKN + (size_t)(q0 + 1) * MASKN + 1;

    const int row = tid & 63, seg = tid >> 6;
    __syncthreads();

    for (int kt = 0; kt < Nn; kt += BN) {
        // ---- Load K (row-major, padded) and V tiles ----
        const float4* Kg = (const float4*)(k + ((size_t)b * Nn + kt) * Dd);
        const float4* Vg = (const float4*)(v + ((size_t)b * Nn + kt) * Dd);
#pragma unroll
        for (int i = 0; i < 4; i++) {
            int f = tid + i * 512;           // 0..2047
            int r = f >> 5, c4 = f & 31;
            *(float4*)&Ks[r * KP + c4 * 4] = Kg[f];
            ((float4*)Vs)[f] = Vg[f];
        }
        __syncthreads();

        // ---- Scores: S = Qs . Ks^T (Q pre-scaled) ----
        float s[2][4];
#pragma unroll
        for (int i = 0; i < 2; i++)
#pragma unroll
            for (int j = 0; j < 4; j++) s[i][j] = 0.0f;

        const float* q0p = &Qs[(2 * sy) * 128];
        const float* q1p = &Qs[(2 * sy + 1) * 128];
#pragma unroll 4
        for (int d = 0; d < 128; d += 4) {
            float4 qa = *(const float4*)(q0p + d);
            float4 qb = *(const float4*)(q1p + d);
#pragma unroll
            for (int j = 0; j < 4; j++) {
                float4 kv = *(const float4*)&Ks[(sx + 16 * j) * KP + d];
                s[0][j] += qa.x * kv.x + qa.y * kv.y + qa.z * kv.z + qa.w * kv.w;
                s[1][j] += qb.x * kv.x + qb.y * kv.y + qb.z * kv.z + qb.w * kv.w;
            }
        }

        // ---- Apply mask (int32: nonzero => masked), write to Ss ----
#pragma unroll
        for (int i = 0; i < 2; i++) {
            const int* mr = mb + (size_t)(2 * sy + i) * MASKN + kt;
#pragma unroll
            for (int j = 0; j < 4; j++) {
                int col = sx + 16 * j;
                int mm = __ldg(&mr[col]);
                Ss[(2 * sy + i) * SP + col] = mm ? NEGINF : s[i][j];
            }
        }
        __syncthreads();

        // ---- Softmax pass 1: tile row max (8 segments of 8 cols) ----
        {
            float tm = NEGINF;
            const float* sr = &Ss[row * SP + seg * 8];
#pragma unroll
            for (int c = 0; c < 8; c++) tm = fmaxf(tm, sr[c]);
            red[seg * 64 + row] = tm;
        }
        __syncthreads();
        if (tid < 64) {
            float m_old = m_s[tid];
            float m_new = m_old;
#pragma unroll
            for (int s2 = 0; s2 < 8; s2++) m_new = fmaxf(m_new, red[s2 * 64 + tid]);
            float corr;
            if (m_new == NEGINF) corr = 1.0f;            // nothing unmasked yet
            else corr = __expf(m_old - m_new);           // m_old=-inf -> 0
            m_s[tid] = m_new;
            corr_s[tid] = corr;
        }
        __syncthreads();

        // ---- Softmax pass 2: p = exp(s - m), partial row sums ----
        {
            float mrow = m_s[row];
            float* sr = &Ss[row * SP + seg * 8];
            float psum = 0.0f;
            if (mrow == NEGINF) {
#pragma unroll
                for (int c = 0; c < 8; c++) sr[c] = 0.0f;
            } else {
#pragma unroll
                for (int c = 0; c < 8; c++) {
                    float p = __expf(sr[c] - mrow);
                    sr[c] = p;
                    psum += p;
                }
            }
            red[seg * 64 + row] = psum;
        }
        __syncthreads();
        if (tid < 64) {
            float ssum = 0.0f;
#pragma unroll
            for (int s2 = 0; s2 < 8; s2++) ssum += red[s2 * 64 + tid];
            l_s[tid] = l_s[tid] * corr_s[tid] + ssum;
        }

        // ---- Rescale accumulators, O += P . V ----
        {
            float c0 = corr_s[2 * vy], c1 = corr_s[2 * vy + 1];
#pragma unroll
            for (int j = 0; j < 8; j++) { acc[0][j] *= c0; acc[1][j] *= c1; }

            const float* p0r = &Ss[(2 * vy) * SP];
            const float* p1r = &Ss[(2 * vy + 1) * SP];
#pragma unroll 4
            for (int kk = 0; kk < BN; kk++) {
                float p0 = p0r[kk];
                float p1 = p1r[kk];
                const float* vr = &Vs[kk * 128 + 4 * vx];
                float4 va = *(const float4*)vr;
                float4 vb = *(const float4*)(vr + 64);
                acc[0][0] += p0 * va.x; acc[0][1] += p0 * va.y;
                acc[0][2] += p0 * va.z; acc[0][3] += p0 * va.w;
                acc[0][4] += p0 * vb.x; acc[0][5] += p0 * vb.y;
                acc[0][6] += p0 * vb.z; acc[0][7] += p0 * vb.w;
                acc[1][0] += p1 * va.x; acc[1][1] += p1 * va.y;
                acc[1][2] += p1 * va.z; acc[1][3] += p1 * va.w;
                acc[1][4] += p1 * vb.x; acc[1][5] += p1 * vb.y;
                acc[1][6] += p1 * vb.z; acc[1][7] += p1 * vb.w;
            }
        }
        __syncthreads();  // protect Ks/Vs/Ss/red before next tile
    }

    // ---- Epilogue: out = O / l  (l==0 -> 0, matches NaN->0 semantics) ----
    float l0 = l_s[2 * vy], l1 = l_s[2 * vy + 1];
    float inv0 = (l0 > 0.0f) ? 1.0f / l0 : 0.0f;
    float inv1 = (l1 > 0.0f) ? 1.0f / l1 : 0.0f;
    float* ob = out + ((size_t)b * Nn + q0) * Dd;
    float* r0 = ob + (size_t)(2 * vy) * Dd + 4 * vx;
    float* r1 = ob + (size_t)(2 * vy + 1) * Dd + 4 * vx;
    *(float4*)r0 = make_float4(acc[0][0] * inv0, acc[0][1] * inv0,
                               acc[0][2] * inv0, acc[0][3] * inv0);
    *(float4*)(r0 + 64) = make_float4(acc[0][4] * inv0, acc[0][5] * inv0,
                                      acc[0][6] * inv0, acc[0][7] * inv0);
    *(float4*)r1 = make_float4(acc[1][0] * inv1, acc[1][1] * inv1,
                               acc[1][2] * inv1, acc[1][3] * inv1);
    *(float4*)(r1 + 64) = make_float4(acc[1][4] * inv1, acc[1][5] * inv1,
                                      acc[1][6] * inv1, acc[1][7] * inv1);
}

// ---------------------------------------------------------------------------
// Launch: q/k/v projections -> flash attention -> output projection.
// ---------------------------------------------------------------------------
extern "C" void kernel_launch(void* const* d_in, const int* in_sizes, int n_in,
                              void* d_out, int out_size) {
    const float* query = (const float*)d_in[0];
    const float* key_  = (const float*)d_in[1];
    const int*   mask  = (const int*)d_in[2];
    const float* Wq = (const float*)d_in[3];
    const float* bq = (const float*)d_in[4];
    const float* Wk = (const float*)d_in[5];
    const float* bk = (const float*)d_in[6];
    const float* Wv = (const float*)d_in[7];
    const float* bv = (const float*)d_in[8];
    const float* Wo = (const float*)d_in[9];
    const float* bo = (const float*)d_in[10];
    float* out = (float*)d_out;

    float *qb, *kb, *vb, *ab;
    cudaGetSymbolAddress((void**)&qb, g_q);
    cudaGetSymbolAddress((void**)&kb, g_k);
    cudaGetSymbolAddress((void**)&vb, g_v);
    cudaGetSymbolAddress((void**)&ab, g_ao);

    const int nblk = MROWS / 64;  // 512

    proj_kernel<<<nblk, 256>>>(query, Wq, bq, qb);
    proj_kernel<<<nblk, 256>>>(key_, Wk, bk, kb);
    proj_kernel<<<nblk, 256>>>(kb, Wv, bv, vb);   // v = projected_k @ Wv + bv

    size_t smem_bytes = (size_t)ATTN_SMEM_FLOATS * sizeof(float);
    cudaFuncSetAttribute(attn_kernel, cudaFuncAttributeMaxDynamicSharedMemorySize,
                         (int)smem_bytes);
    attn_kernel<<<dim3(Nn / BM, Bb), 512, smem_bytes>>>(qb, kb, vb, mask, ab);

    proj_kernel<<<nblk, 256>>>(ab, Wo, bo, out);
}

// round 3
// speedup vs baseline: 2.5282x; 2.5282x over previous
#include <cuda_runtime.h>

// Problem constants
#define Bb 16
#define Nn 2048
#define Dd 128
#define MASKN 2049
#define MROWS (Bb * Nn)

#define NEGINF __int_as_float(0xff800000)

// Scratch (allocation-free rule: __device__ globals)
__device__ float g_q[MROWS * Dd];
__device__ float g_k[MROWS * Dd];
__device__ float g_v[MROWS * Dd];
__device__ float g_ao[MROWS * Dd];

// ---------------------------------------------------------------------------
// Projection: Y[M,128] = X[M,128] @ W[128,128] + bias (fp32, unchanged)
// ---------------------------------------------------------------------------
__global__ __launch_bounds__(256) void proj_kernel(
    const float* __restrict__ X, const float* __restrict__ W,
    const float* __restrict__ bias, float* __restrict__ Y) {
    __shared__ float Xs[64 * 128];
    const int tid = threadIdx.x;
    const size_t row0 = (size_t)blockIdx.x * 64;

    const float4* Xg = (const float4*)(X + row0 * Dd);
    float4* Xs4 = (float4*)Xs;
#pragma unroll
    for (int i = 0; i < 8; i++) Xs4[tid + i * 256] = Xg[tid + i * 256];
    __syncthreads();

    const int ty = tid >> 4, tx = tid & 15;
    const float4* W4 = (const float4*)W;

    float acc[4][8];
#pragma unroll
    for (int i = 0; i < 4; i++)
#pragma unroll
        for (int j = 0; j < 8; j++) acc[i][j] = 0.0f;

#pragma unroll 4
    for (int kk = 0; kk < 128; kk++) {
        float4 w0 = __ldg(&W4[kk * 32 + tx]);
        float4 w1 = __ldg(&W4[kk * 32 + tx + 16]);
#pragma unroll
        for (int i = 0; i < 4; i++) {
            float xv = Xs[(4 * ty + i) * 128 + kk];
            acc[i][0] += xv * w0.x; acc[i][1] += xv * w0.y;
            acc[i][2] += xv * w0.z; acc[i][3] += xv * w0.w;
            acc[i][4] += xv * w1.x; acc[i][5] += xv * w1.y;
            acc[i][6] += xv * w1.z; acc[i][7] += xv * w1.w;
        }
    }

    float4 b0 = __ldg(&((const float4*)bias)[tx]);
    float4 b1 = __ldg(&((const float4*)bias)[tx + 16]);
#pragma unroll
    for (int i = 0; i < 4; i++) {
        float4 o0 = make_float4(acc[i][0] + b0.x, acc[i][1] + b0.y,
                                acc[i][2] + b0.z, acc[i][3] + b0.w);
        float4 o1 = make_float4(acc[i][4] + b1.x, acc[i][5] + b1.y,
                                acc[i][6] + b1.z, acc[i][7] + b1.w);
        float4* yr = (float4*)(Y + (row0 + 4 * ty + i) * Dd);
        yr[tx] = o0;
        yr[tx + 16] = o1;
    }
}

// ---------------------------------------------------------------------------
// Flash attention with tf32 mma.sync (m16n8k8), fp32 accumulate + softmax.
// CTA: 256 threads (8 warps), BM=64 queries, BN=64 keys per tile.
// Warp (wy=warp>>1, wx=warp&1): S tile rows 16*wy, cols 32*wx;
//                               O tile rows 16*wy, cols 64*wx.
// Smem pads chosen for conflict-free fragment gathers:
//   LDQ/LDK=132 (bank = 4g+tg), LDV=136 (bank = 8tg+g), LDP=68.
// ---------------------------------------------------------------------------
#define LDQ 132
#define LDK 132
#define LDV 136
#define LDP 68

#define Q_OFF   0
#define K_OFF   (64 * LDQ)                 // 8448
#define V_OFF   (K_OFF + 64 * LDK)         // 16896
#define P_OFF   (V_OFF + 64 * LDV)         // 25600
#define MS_OFF  (P_OFF + 64 * LDP)         // 29952
#define LS_OFF  (MS_OFF + 64)
#define CR_OFF  (LS_OFF + 64)
#define RM_OFF  (CR_OFF + 64)
#define RS_OFF  (RM_OFF + 128)
#define ATTN_SMEM_FLOATS (RS_OFF + 128)    // 30400 floats = 121.6 KB

__device__ __forceinline__ float to_tf32(float x) {
    float y;
    asm("cvt.rna.tf32.f32 %0, %1;" : "=f"(y) : "f"(x));
    return y;
}

__device__ __forceinline__ void mma_tf32(float c[4],
                                         unsigned a0, unsigned a1,
                                         unsigned a2, unsigned a3,
                                         unsigned b0, unsigned b1) {
    asm volatile(
        "mma.sync.aligned.m16n8k8.row.col.f32.tf32.tf32.f32 "
        "{%0,%1,%2,%3},{%4,%5,%6,%7},{%8,%9},{%0,%1,%2,%3};\n"
        : "+f"(c[0]), "+f"(c[1]), "+f"(c[2]), "+f"(c[3])
        : "r"(a0), "r"(a1), "r"(a2), "r"(a3), "r"(b0), "r"(b1));
}

__global__ __launch_bounds__(256, 1) void attn_kernel(
    const float* __restrict__ q, const float* __restrict__ k,
    const float* __restrict__ v, const int* __restrict__ mask,
    float* __restrict__ out) {
    extern __shared__ float sm[];
    float* Qs = sm + Q_OFF;
    float* Ks = sm + K_OFF;
    float* Vs = sm + V_OFF;
    float* Ps = sm + P_OFF;
    float* m_s = sm + MS_OFF;
    float* l_s = sm + LS_OFF;
    float* cr_s = sm + CR_OFF;
    float* redm = sm + RM_OFF;
    float* reds = sm + RS_OFF;

    const int tid = threadIdx.x;
    const int lane = tid & 31, warp = tid >> 5;
    const int g = lane >> 2, tg = lane & 3;
    const int wy = warp >> 1, wx = warp & 1;
    const int b = blockIdx.y;
    const int q0 = blockIdx.x * 64;
    const float SCALE = 0.08838834764831845f;  // 1/sqrt(128)

    // Load Q tile, pre-scaled, rounded to tf32
    const float4* Qg = (const float4*)(q + ((size_t)b * Nn + q0) * Dd);
#pragma unroll
    for (int i = 0; i < 8; i++) {
        int f = tid + i * 256;
        float4 t = Qg[f];
        t.x = to_tf32(t.x * SCALE); t.y = to_tf32(t.y * SCALE);
        t.z = to_tf32(t.z * SCALE); t.w = to_tf32(t.w * SCALE);
        int r = f >> 5, c = (f & 31) * 4;
        *(float4*)&Qs[r * LDQ + c] = t;
    }
    if (tid < 64) { m_s[tid] = NEGINF; l_s[tid] = 0.0f; }

    const int r0 = 16 * wy + g, r1 = r0 + 8;

    float oc[8][4];
#pragma unroll
    for (int nt = 0; nt < 8; nt++)
#pragma unroll
        for (int j = 0; j < 4; j++) oc[nt][j] = 0.0f;

    const int* mb =
        mask + (size_t)b * MASKN * MASKN + (size_t)(q0 + 1) * MASKN + 1;
    __syncthreads();

    for (int kt = 0; kt < Nn; kt += 64) {
        // ---- Load K, V tiles (tf32-rounded) ----
        const float4* Kg = (const float4*)(k + ((size_t)b * Nn + kt) * Dd);
        const float4* Vg = (const float4*)(v + ((size_t)b * Nn + kt) * Dd);
#pragma unroll
        for (int i = 0; i < 8; i++) {
            int f = tid + i * 256;
            int r = f >> 5, c = (f & 31) * 4;
            float4 tk = Kg[f], tv = Vg[f];
            tk.x = to_tf32(tk.x); tk.y = to_tf32(tk.y);
            tk.z = to_tf32(tk.z); tk.w = to_tf32(tk.w);
            tv.x = to_tf32(tv.x); tv.y = to_tf32(tv.y);
            tv.z = to_tf32(tv.z); tv.w = to_tf32(tv.w);
            *(float4*)&Ks[r * LDK + c] = tk;
            *(float4*)&Vs[r * LDV + c] = tv;
        }
        __syncthreads();

        // ---- S = Q.K^T via tf32 mma ----
        float sc[4][4];
#pragma unroll
        for (int nt = 0; nt < 4; nt++)
#pragma unroll
            for (int j = 0; j < 4; j++) sc[nt][j] = 0.0f;

#pragma unroll
        for (int s = 0; s < 16; s++) {
            int d0 = 8 * s;
            unsigned a0 = __float_as_uint(Qs[r0 * LDQ + d0 + tg]);
            unsigned a1 = __float_as_uint(Qs[r1 * LDQ + d0 + tg]);
            unsigned a2 = __float_as_uint(Qs[r0 * LDQ + d0 + tg + 4]);
            unsigned a3 = __float_as_uint(Qs[r1 * LDQ + d0 + tg + 4]);
#pragma unroll
            for (int nt = 0; nt < 4; nt++) {
                int n = 32 * wx + 8 * nt + g;
                unsigned b0 = __float_as_uint(Ks[n * LDK + d0 + tg]);
                unsigned b1 = __float_as_uint(Ks[n * LDK + d0 + tg + 4]);
                mma_tf32(sc[nt], a0, a1, a2, a3, b0, b1);
            }
        }

        // ---- Mask in registers ----
#pragma unroll
        for (int nt = 0; nt < 4; nt++) {
            int cbase = 32 * wx + 8 * nt + 2 * tg;
            const int* mr0 = mb + (size_t)r0 * MASKN + kt + cbase;
            const int* mr1 = mb + (size_t)r1 * MASKN + kt + cbase;
            if (__ldg(mr0))     sc[nt][0] = NEGINF;
            if (__ldg(mr0 + 1)) sc[nt][1] = NEGINF;
            if (__ldg(mr1))     sc[nt][2] = NEGINF;
            if (__ldg(mr1 + 1)) sc[nt][3] = NEGINF;
        }

        // ---- Row max (registers + shfl over quad, combine 2 warps in smem) ----
        float rm0 = NEGINF, rm1 = NEGINF;
#pragma unroll
        for (int nt = 0; nt < 4; nt++) {
            rm0 = fmaxf(rm0, fmaxf(sc[nt][0], sc[nt][1]));
            rm1 = fmaxf(rm1, fmaxf(sc[nt][2], sc[nt][3]));
        }
        rm0 = fmaxf(rm0, __shfl_xor_sync(0xffffffffu, rm0, 1));
        rm0 = fmaxf(rm0, __shfl_xor_sync(0xffffffffu, rm0, 2));
        rm1 = fmaxf(rm1, __shfl_xor_sync(0xffffffffu, rm1, 1));
        rm1 = fmaxf(rm1, __shfl_xor_sync(0xffffffffu, rm1, 2));
        if (tg == 0) {
            redm[wx * 64 + r0] = rm0;
            redm[wx * 64 + r1] = rm1;
        }
        __syncthreads();
        if (tid < 64) {
            float mo = m_s[tid];
            float mn = fmaxf(mo, fmaxf(redm[tid], redm[64 + tid]));
            float corr = (mn == NEGINF) ? 1.0f : __expf(mo - mn);
            m_s[tid] = mn;
            cr_s[tid] = corr;
        }
        __syncthreads();

        // ---- p = exp(s - m); write P (tf32) to smem; row sums ----
        float m0 = m_s[r0], m1 = m_s[r1];
        float ps0 = 0.0f, ps1 = 0.0f;
#pragma unroll
        for (int nt = 0; nt < 4; nt++) {
            float p0 = (m0 == NEGINF) ? 0.0f : __expf(sc[nt][0] - m0);
            float p1 = (m0 == NEGINF) ? 0.0f : __expf(sc[nt][1] - m0);
            float p2 = (m1 == NEGINF) ? 0.0f : __expf(sc[nt][2] - m1);
            float p3 = (m1 == NEGINF) ? 0.0f : __expf(sc[nt][3] - m1);
            ps0 += p0 + p1;
            ps1 += p2 + p3;
            int col = 32 * wx + 8 * nt + 2 * tg;
            *(float2*)&Ps[r0 * LDP + col] = make_float2(to_tf32(p0), to_tf32(p1));
            *(float2*)&Ps[r1 * LDP + col] = make_float2(to_tf32(p2), to_tf32(p3));
        }
        ps0 += __shfl_xor_sync(0xffffffffu, ps0, 1);
        ps0 += __shfl_xor_sync(0xffffffffu, ps0, 2);
        ps1 += __shfl_xor_sync(0xffffffffu, ps1, 1);
        ps1 += __shfl_xor_sync(0xffffffffu, ps1, 2);
        if (tg == 0) {
            reds[wx * 64 + r0] = ps0;
            reds[wx * 64 + r1] = ps1;
        }
        __syncthreads();
        if (tid < 64)
            l_s[tid] = l_s[tid] * cr_s[tid] + reds[tid] + reds[64 + tid];

        // ---- Rescale O, then O += P.V via tf32 mma ----
        float c0 = cr_s[r0], c1 = cr_s[r1];
#pragma unroll
        for (int nt = 0; nt < 8; nt++) {
            oc[nt][0] *= c0; oc[nt][1] *= c0;
            oc[nt][2] *= c1; oc[nt][3] *= c1;
        }
#pragma unroll
        for (int s = 0; s < 8; s++) {
            int k0 = 8 * s;
            unsigned a0 = __float_as_uint(Ps[r0 * LDP + k0 + tg]);
            unsigned a1 = __float_as_uint(Ps[r1 * LDP + k0 + tg]);
            unsigned a2 = __float_as_uint(Ps[r0 * LDP + k0 + tg + 4]);
            unsigned a3 = __float_as_uint(Ps[r1 * LDP + k0 + tg + 4]);
#pragma unroll
            for (int nt = 0; nt < 8; nt++) {
                int n = 64 * wx + 8 * nt + g;
                unsigned b0 = __float_as_uint(Vs[(k0 + tg) * LDV + n]);
                unsigned b1 = __float_as_uint(Vs[(k0 + tg + 4) * LDV + n]);
                mma_tf32(oc[nt], a0, a1, a2, a3, b0, b1);
            }
        }
        __syncthreads();  // protect Ks/Vs/Ps/red before next tile
    }

    // ---- Epilogue: out = O / l (l==0 -> 0, matches NaN->0 semantics) ----
    float l0 = l_s[r0], l1 = l_s[r1];
    float i0 = (l0 > 0.0f) ? 1.0f / l0 : 0.0f;
    float i1 = (l1 > 0.0f) ? 1.0f / l1 : 0.0f;
    float* ob = out + ((size_t)b * Nn + q0) * Dd;
#pragma unroll
    for (int nt = 0; nt < 8; nt++) {
        int col = 64 * wx + 8 * nt + 2 * tg;
        *(float2*)&ob[(size_t)r0 * Dd + col] =
            make_float2(oc[nt][0] * i0, oc[nt][1] * i0);
        *(float2*)&ob[(size_t)r1 * Dd + col] =
            make_float2(oc[nt][2] * i1, oc[nt][3] * i1);
    }
}

// ---------------------------------------------------------------------------
// Launch: q/k/v projections -> flash attention (tf32 mma) -> output projection.
// ---------------------------------------------------------------------------
extern "C" void kernel_launch(void* const* d_in, const int* in_sizes, int n_in,
                              void* d_out, int out_size) {
    const float* query = (const float*)d_in[0];
    const float* key_  = (const float*)d_in[1];
    const int*   mask  = (const int*)d_in[2];
    const float* Wq = (const float*)d_in[3];
    const float* bq = (const float*)d_in[4];
    const float* Wk = (const float*)d_in[5];
    const float* bk = (const float*)d_in[6];
    const float* Wv = (const float*)d_in[7];
    const float* bv = (const float*)d_in[8];
    const float* Wo = (const float*)d_in[9];
    const float* bo = (const float*)d_in[10];
    float* out = (float*)d_out;

    float *qb, *kb, *vb, *ab;
    cudaGetSymbolAddress((void**)&qb, g_q);
    cudaGetSymbolAddress((void**)&kb, g_k);
    cudaGetSymbolAddress((void**)&vb, g_v);
    cudaGetSymbolAddress((void**)&ab, g_ao);

    const int nblk = MROWS / 64;  // 512

    proj_kernel<<<nblk, 256>>>(query, Wq, bq, qb);
    proj_kernel<<<nblk, 256>>>(key_, Wk, bk, kb);
    proj_kernel<<<nblk, 256>>>(kb, Wv, bv, vb);   // v = projected_k @ Wv + bv

    size_t smem_bytes = (size_t)ATTN_SMEM_FLOATS * sizeof(float);
    cudaFuncSetAttribute(attn_kernel, cudaFuncAttributeMaxDynamicSharedMemorySize,
                         (int)smem_bytes);
    attn_kernel<<<dim3(Nn / 64, Bb), 256, smem_bytes>>>(qb, kb, vb, mask, ab);

    proj_kernel<<<nblk, 256>>>(ab, Wo, bo, out);
}

// round 6
// speedup vs baseline: 2.8114x; 1.1120x over previous
#include <cuda_runtime.h>
#include <cstdint>

// Problem constants
#define Bb 16
#define Nn 2048
#define Dd 128
#define MASKN 2049
#define MROWS (Bb * Nn)

#define NEGINF __int_as_float(0xff800000)

// Scratch (allocation-free rule: __device__ globals)
__device__ float g_q[MROWS * Dd];
__device__ float g_k[MROWS * Dd];
__device__ float g_v[MROWS * Dd];
__device__ float g_ao[MROWS * Dd];

__device__ __forceinline__ float to_tf32(float x) {
    float y;
    asm("cvt.rna.tf32.f32 %0, %1;" : "=f"(y) : "f"(x));
    return y;
}

// ---------------------------------------------------------------------------
// Projection: Y[M,128] = X[M,128] @ W[128,128] + bias (fp32 compute).
// ROUND: store outputs RNA-rounded to tf32 (for buffers consumed by tensor
// core MMAs downstream — removes truncation bias in the attention GEMMs).
// ---------------------------------------------------------------------------
template <bool ROUND>
__global__ __launch_bounds__(256) void proj_kernel(
    const float* __restrict__ X, const float* __restrict__ W,
    const float* __restrict__ bias, float* __restrict__ Y) {
    __shared__ float Xs[64 * 128];
    const int tid = threadIdx.x;
    const size_t row0 = (size_t)blockIdx.x * 64;

    const float4* Xg = (const float4*)(X + row0 * Dd);
    float4* Xs4 = (float4*)Xs;
#pragma unroll
    for (int i = 0; i < 8; i++) Xs4[tid + i * 256] = Xg[tid + i * 256];
    __syncthreads();

    const int ty = tid >> 4, tx = tid & 15;
    const float4* W4 = (const float4*)W;

    float acc[4][8];
#pragma unroll
    for (int i = 0; i < 4; i++)
#pragma unroll
        for (int j = 0; j < 8; j++) acc[i][j] = 0.0f;

#pragma unroll 4
    for (int kk = 0; kk < 128; kk++) {
        float4 w0 = __ldg(&W4[kk * 32 + tx]);
        float4 w1 = __ldg(&W4[kk * 32 + tx + 16]);
#pragma unroll
        for (int i = 0; i < 4; i++) {
            float xv = Xs[(4 * ty + i) * 128 + kk];
            acc[i][0] += xv * w0.x; acc[i][1] += xv * w0.y;
            acc[i][2] += xv * w0.z; acc[i][3] += xv * w0.w;
            acc[i][4] += xv * w1.x; acc[i][5] += xv * w1.y;
            acc[i][6] += xv * w1.z; acc[i][7] += xv * w1.w;
        }
    }

    float4 b0 = __ldg(&((const float4*)bias)[tx]);
    float4 b1 = __ldg(&((const float4*)bias)[tx + 16]);
#pragma unroll
    for (int i = 0; i < 4; i++) {
        float4 o0 = make_float4(acc[i][0] + b0.x, acc[i][1] + b0.y,
                                acc[i][2] + b0.z, acc[i][3] + b0.w);
        float4 o1 = make_float4(acc[i][4] + b1.x, acc[i][5] + b1.y,
                                acc[i][6] + b1.z, acc[i][7] + b1.w);
        if (ROUND) {
            o0.x = to_tf32(o0.x); o0.y = to_tf32(o0.y);
            o0.z = to_tf32(o0.z); o0.w = to_tf32(o0.w);
            o1.x = to_tf32(o1.x); o1.y = to_tf32(o1.y);
            o1.z = to_tf32(o1.z); o1.w = to_tf32(o1.w);
        }
        float4* yr = (float4*)(Y + (row0 + 4 * ty + i) * Dd);
        yr[tx] = o0;
        yr[tx + 16] = o1;
    }
}

// ---------------------------------------------------------------------------
// Flash attention, tf32 mma.sync m16n8k8, cp.async double-buffered K/V.
// Pipeline: wait_group 0 -> __syncthreads -> issue prefetch(nxt) -> compute.
// K/V arrive pre-rounded (RNA) from the projection kernels; Q rounded at
// load (post-scale); P rounded (RNA) before the Ps store.
// ---------------------------------------------------------------------------
#define LDQ 132
#define LDK 132
#define LDV 136
#define LDP 68

#define Q_OFF   0
#define K_OFF   (64 * LDQ)                  // 8448
#define KSTAGE  (64 * LDK)                  // 8448
#define V_OFF   (K_OFF + 2 * KSTAGE)        // 25344
#define VSTAGE  (64 * LDV)                  // 8704
#define P_OFF   (V_OFF + 2 * VSTAGE)        // 42752
#define RM_OFF  (P_OFF + 64 * LDP)          // 47104
#define RS_OFF  (RM_OFF + 128)
#define ATTN_SMEM_FLOATS (RS_OFF + 128)     // 47360 floats = 185 KB

__device__ __forceinline__ void cp16(uint32_t dst, const void* src) {
    asm volatile("cp.async.cg.shared.global [%0], [%1], 16;"
                 :: "r"(dst), "l"(src));
}

__device__ __forceinline__ void mma_tf32(float c[4],
                                         unsigned a0, unsigned a1,
                                         unsigned a2, unsigned a3,
                                         unsigned b0, unsigned b1) {
    asm volatile(
        "mma.sync.aligned.m16n8k8.row.col.f32.tf32.tf32.f32 "
        "{%0,%1,%2,%3},{%4,%5,%6,%7},{%8,%9},{%0,%1,%2,%3};\n"
        : "+f"(c[0]), "+f"(c[1]), "+f"(c[2]), "+f"(c[3])
        : "r"(a0), "r"(a1), "r"(a2), "r"(a3), "r"(b0), "r"(b1));
}

__global__ __launch_bounds__(256, 1) void attn_kernel(
    const float* __restrict__ q, const float* __restrict__ k,
    const float* __restrict__ v, const int* __restrict__ mask,
    float* __restrict__ out) {
    extern __shared__ float sm[];
    float* Qs = sm + Q_OFF;
    float* Ps = sm + P_OFF;
    float* redm = sm + RM_OFF;
    float* reds = sm + RS_OFF;

    const int tid = threadIdx.x;
    const int lane = tid & 31, warp = tid >> 5;
    const int g = lane >> 2, tg = lane & 3;
    const int wy = warp >> 1, wx = warp & 1;
    const int b = blockIdx.y;
    const int q0 = blockIdx.x * 64;
    const float SCALE = 0.08838834764831845f;  // 1/sqrt(128)

    const uint32_t sm_u32 = (uint32_t)__cvta_generic_to_shared(sm);
    const uint32_t k_u32 = sm_u32 + K_OFF * 4;
    const uint32_t v_u32 = sm_u32 + V_OFF * 4;

    // Load Q tile, pre-scaled, RNA tf32-rounded
    const float4* Qg = (const float4*)(q + ((size_t)b * Nn + q0) * Dd);
#pragma unroll
    for (int i = 0; i < 8; i++) {
        int f = tid + i * 256;
        float4 t = Qg[f];
        t.x = to_tf32(t.x * SCALE); t.y = to_tf32(t.y * SCALE);
        t.z = to_tf32(t.z * SCALE); t.w = to_tf32(t.w * SCALE);
        int r = f >> 5, c = (f & 31) * 4;
        *(float4*)&Qs[r * LDQ + c] = t;
    }

    const int r0 = 16 * wy + g, r1 = r0 + 8;

    float oc[8][4];
#pragma unroll
    for (int nt = 0; nt < 8; nt++)
#pragma unroll
        for (int j = 0; j < 4; j++) oc[nt][j] = 0.0f;

    // Softmax state in registers (replicated across the 8 threads owning a row)
    float m0 = NEGINF, m1 = NEGINF, l0 = 0.0f, l1 = 0.0f;

    const int* mb =
        mask + (size_t)b * MASKN * MASKN + (size_t)(q0 + 1) * MASKN + 1;

    // Prefetch K/V tile 0 into stage 0
    {
        const float4* Kg = (const float4*)(k + ((size_t)b * Nn) * Dd);
        const float4* Vg = (const float4*)(v + ((size_t)b * Nn) * Dd);
#pragma unroll
        for (int i = 0; i < 8; i++) {
            int f = tid + i * 256;
            int r = f >> 5, c = (f & 31) * 4;
            cp16(k_u32 + (uint32_t)(r * LDK + c) * 4, Kg + f);
            cp16(v_u32 + (uint32_t)(r * LDV + c) * 4, Vg + f);
        }
        asm volatile("cp.async.commit_group;");
    }

    for (int ti = 0; ti < Nn / 64; ti++) {
        const int kt = ti * 64;
        const int cur = ti & 1;
        float* Ksc = sm + K_OFF + cur * KSTAGE;
        float* Vsc = sm + V_OFF + cur * VSTAGE;

        // Stage `cur` ready for this thread...
        asm volatile("cp.async.wait_group 0;" ::: "memory");
        // ...and for all threads; proves everyone finished reading stage
        // `nxt` in the previous iteration (WAR protection).
        __syncthreads();

        // Safe now to issue next tile's loads into the other stage.
        if (ti + 1 < Nn / 64) {
            const int nxt = cur ^ 1;
            const float4* Kg =
                (const float4*)(k + ((size_t)b * Nn + kt + 64) * Dd);
            const float4* Vg =
                (const float4*)(v + ((size_t)b * Nn + kt + 64) * Dd);
            uint32_t kb = k_u32 + (uint32_t)(nxt * KSTAGE) * 4;
            uint32_t vb = v_u32 + (uint32_t)(nxt * VSTAGE) * 4;
#pragma unroll
            for (int i = 0; i < 8; i++) {
                int f = tid + i * 256;
                int r = f >> 5, c = (f & 31) * 4;
                cp16(kb + (uint32_t)(r * LDK + c) * 4, Kg + f);
                cp16(vb + (uint32_t)(r * LDV + c) * 4, Vg + f);
            }
            asm volatile("cp.async.commit_group;");
        }

        // ---- Mask prefetch into registers (consumed after S MMAs) ----
        int mk[16];
#pragma unroll
        for (int nt = 0; nt < 4; nt++) {
            int cb = 32 * wx + 8 * nt + 2 * tg;
            const int* mr0 = mb + (size_t)r0 * MASKN + kt + cb;
            const int* mr1 = mb + (size_t)r1 * MASKN + kt + cb;
            mk[4 * nt + 0] = __ldg(mr0);
            mk[4 * nt + 1] = __ldg(mr0 + 1);
            mk[4 * nt + 2] = __ldg(mr1);
            mk[4 * nt + 3] = __ldg(mr1 + 1);
        }

        // ---- S = Q.K^T via tf32 mma (operands pre-rounded RNA) ----
        float sc[4][4];
#pragma unroll
        for (int nt = 0; nt < 4; nt++)
#pragma unroll
            for (int j = 0; j < 4; j++) sc[nt][j] = 0.0f;

#pragma unroll
        for (int s = 0; s < 16; s++) {
            int d0 = 8 * s;
            unsigned a0 = __float_as_uint(Qs[r0 * LDQ + d0 + tg]);
            unsigned a1 = __float_as_uint(Qs[r1 * LDQ + d0 + tg]);
            unsigned a2 = __float_as_uint(Qs[r0 * LDQ + d0 + tg + 4]);
            unsigned a3 = __float_as_uint(Qs[r1 * LDQ + d0 + tg + 4]);
#pragma unroll
            for (int nt = 0; nt < 4; nt++) {
                int n = 32 * wx + 8 * nt + g;
                unsigned b0 = __float_as_uint(Ksc[n * LDK + d0 + tg]);
                unsigned b1 = __float_as_uint(Ksc[n * LDK + d0 + tg + 4]);
                mma_tf32(sc[nt], a0, a1, a2, a3, b0, b1);
            }
        }

        // ---- Apply mask ----
#pragma unroll
        for (int nt = 0; nt < 4; nt++) {
            if (mk[4 * nt + 0]) sc[nt][0] = NEGINF;
            if (mk[4 * nt + 1]) sc[nt][1] = NEGINF;
            if (mk[4 * nt + 2]) sc[nt][2] = NEGINF;
            if (mk[4 * nt + 3]) sc[nt][3] = NEGINF;
        }

        // ---- Row max: quad shfl, then exchange between the pair's 2 warps ----
        float rm0 = NEGINF, rm1 = NEGINF;
#pragma unroll
        for (int nt = 0; nt < 4; nt++) {
            rm0 = fmaxf(rm0, fmaxf(sc[nt][0], sc[nt][1]));
            rm1 = fmaxf(rm1, fmaxf(sc[nt][2], sc[nt][3]));
        }
        rm0 = fmaxf(rm0, __shfl_xor_sync(0xffffffffu, rm0, 1));
        rm0 = fmaxf(rm0, __shfl_xor_sync(0xffffffffu, rm0, 2));
        rm1 = fmaxf(rm1, __shfl_xor_sync(0xffffffffu, rm1, 1));
        rm1 = fmaxf(rm1, __shfl_xor_sync(0xffffffffu, rm1, 2));
        if (tg == 0) {
            redm[wy * 32 + wx * 16 + g] = rm0;
            redm[wy * 32 + wx * 16 + g + 8] = rm1;
        }
        asm volatile("bar.sync %0, %1;" :: "r"(wy + 1), "r"(64) : "memory");

        float tmx0 = fmaxf(redm[wy * 32 + g], redm[wy * 32 + 16 + g]);
        float tmx1 = fmaxf(redm[wy * 32 + g + 8], redm[wy * 32 + 24 + g]);
        float mn0 = fmaxf(m0, tmx0), mn1 = fmaxf(m1, tmx1);
        float corr0 = (mn0 == NEGINF) ? 1.0f : __expf(m0 - mn0);
        float corr1 = (mn1 == NEGINF) ? 1.0f : __expf(m1 - mn1);
        m0 = mn0; m1 = mn1;

        // ---- p = exp(s-m); write P (RNA tf32); partial sums ----
        float ps0 = 0.0f, ps1 = 0.0f;
#pragma unroll
        for (int nt = 0; nt < 4; nt++) {
            float p0 = (m0 == NEGINF) ? 0.0f : __expf(sc[nt][0] - m0);
            float p1 = (m0 == NEGINF) ? 0.0f : __expf(sc[nt][1] - m0);
            float p2 = (m1 == NEGINF) ? 0.0f : __expf(sc[nt][2] - m1);
            float p3 = (m1 == NEGINF) ? 0.0f : __expf(sc[nt][3] - m1);
            ps0 += p0 + p1;
            ps1 += p2 + p3;
            int col = 32 * wx + 8 * nt + 2 * tg;
            *(float2*)&Ps[r0 * LDP + col] = make_float2(to_tf32(p0), to_tf32(p1));
            *(float2*)&Ps[r1 * LDP + col] = make_float2(to_tf32(p2), to_tf32(p3));
        }
        ps0 += __shfl_xor_sync(0xffffffffu, ps0, 1);
        ps0 += __shfl_xor_sync(0xffffffffu, ps0, 2);
        ps1 += __shfl_xor_sync(0xffffffffu, ps1, 1);
        ps1 += __shfl_xor_sync(0xffffffffu, ps1, 2);
        if (tg == 0) {
            reds[wy * 32 + wx * 16 + g] = ps0;
            reds[wy * 32 + wx * 16 + g + 8] = ps1;
        }
        asm volatile("bar.sync %0, %1;" :: "r"(wy + 1), "r"(64) : "memory");

        l0 = l0 * corr0 + reds[wy * 32 + g] + reds[wy * 32 + 16 + g];
        l1 = l1 * corr1 + reds[wy * 32 + g + 8] + reds[wy * 32 + 24 + g];

        // ---- Rescale O; O += P.V via tf32 mma ----
#pragma unroll
        for (int nt = 0; nt < 8; nt++) {
            oc[nt][0] *= corr0; oc[nt][1] *= corr0;
            oc[nt][2] *= corr1; oc[nt][3] *= corr1;
        }
#pragma unroll
        for (int s = 0; s < 8; s++) {
            int k0 = 8 * s;
            unsigned a0 = __float_as_uint(Ps[r0 * LDP + k0 + tg]);
            unsigned a1 = __float_as_uint(Ps[r1 * LDP + k0 + tg]);
            unsigned a2 = __float_as_uint(Ps[r0 * LDP + k0 + tg + 4]);
            unsigned a3 = __float_as_uint(Ps[r1 * LDP + k0 + tg + 4]);
#pragma unroll
            for (int nt = 0; nt < 8; nt++) {
                int n = 64 * wx + 8 * nt + g;
                unsigned b0 = __float_as_uint(Vsc[(k0 + tg) * LDV + n]);
                unsigned b1 = __float_as_uint(Vsc[(k0 + tg + 4) * LDV + n]);
                mma_tf32(oc[nt], a0, a1, a2, a3, b0, b1);
            }
        }
        // K/V stage WAR is protected by the top-of-loop __syncthreads;
        // Ps/redm/reds are pair-private and protected by the pair barriers.
    }

    // ---- Epilogue: out = O / l (l==0 -> 0, matches NaN->0 semantics) ----
    float i0 = (l0 > 0.0f) ? 1.0f / l0 : 0.0f;
    float i1 = (l1 > 0.0f) ? 1.0f / l1 : 0.0f;
    float* ob = out + ((size_t)b * Nn + q0) * Dd;
#pragma unroll
    for (int nt = 0; nt < 8; nt++) {
        int col = 64 * wx + 8 * nt + 2 * tg;
        *(float2*)&ob[(size_t)r0 * Dd + col] =
            make_float2(oc[nt][0] * i0, oc[nt][1] * i0);
        *(float2*)&ob[(size_t)r1 * Dd + col] =
            make_float2(oc[nt][2] * i1, oc[nt][3] * i1);
    }
}

// ---------------------------------------------------------------------------
// Launch: q/k/v projections -> flash attention (tf32 mma) -> output projection.
// k and v buffers are stored RNA-rounded to tf32 (consumed by MMAs only;
// the v-projection reads rounded k, adding ~6e-5 relative — immaterial).
// ---------------------------------------------------------------------------
extern "C" void kernel_launch(void* const* d_in, const int* in_sizes, int n_in,
                              void* d_out, int out_size) {
    const float* query = (const float*)d_in[0];
    const float* key_  = (const float*)d_in[1];
    const int*   mask  = (const int*)d_in[2];
    const float* Wq = (const float*)d_in[3];
    const float* bq = (const float*)d_in[4];
    const float* Wk = (const float*)d_in[5];
    const float* bk = (const float*)d_in[6];
    const float* Wv = (const float*)d_in[7];
    const float* bv = (const float*)d_in[8];
    const float* Wo = (const float*)d_in[9];
    const float* bo = (const float*)d_in[10];
    float* out = (float*)d_out;

    float *qb, *kb, *vb, *ab;
    cudaGetSymbolAddress((void**)&qb, g_q);
    cudaGetSymbolAddress((void**)&kb, g_k);
    cudaGetSymbolAddress((void**)&vb, g_v);
    cudaGetSymbolAddress((void**)&ab, g_ao);

    const int nblk = MROWS / 64;  // 512

    proj_kernel<false><<<nblk, 256>>>(query, Wq, bq, qb);
    proj_kernel<true><<<nblk, 256>>>(key_, Wk, bk, kb);
    proj_kernel<true><<<nblk, 256>>>(kb, Wv, bv, vb);  // v = k_proj @ Wv + bv

    size_t smem_bytes = (size_t)ATTN_SMEM_FLOATS * sizeof(float);
    cudaFuncSetAttribute(attn_kernel, cudaFuncAttributeMaxDynamicSharedMemorySize,
                         (int)smem_bytes);
    attn_kernel<<<dim3(Nn / 64, Bb), 256, smem_bytes>>>(qb, kb, vb, mask, ab);

    proj_kernel<false><<<nblk, 256>>>(ab, Wo, bo, out);
}

// round 7
// speedup vs baseline: 3.0244x; 1.0758x over previous
#include <cuda_runtime.h>
#include <cstdint>

// Problem constants
#define Bb 16
#define Nn 2048
#define Dd 128
#define MASKN 2049
#define MROWS (Bb * Nn)

#define NEGINF __int_as_float(0xff800000)

// Scratch (allocation-free rule: __device__ globals)
__device__ float g_q[MROWS * Dd];
__device__ float g_k[MROWS * Dd];
__device__ float g_v[MROWS * Dd];
__device__ float g_ao[MROWS * Dd];

__device__ __forceinline__ float to_tf32(float x) {
    float y;
    asm("cvt.rna.tf32.f32 %0, %1;" : "=f"(y) : "f"(x));
    return y;
}

// ---------------------------------------------------------------------------
// Projection body: Y[64 rows, 128] = X @ W + bias. ROUND => RNA-tf32 outputs.
// ---------------------------------------------------------------------------
__device__ __forceinline__ void proj_body(
    const float* __restrict__ X, const float* __restrict__ W,
    const float* __restrict__ bias, float* __restrict__ Y,
    size_t row0, bool round_out, float* Xs) {
    const int tid = threadIdx.x;

    const float4* Xg = (const float4*)(X + row0 * Dd);
    float4* Xs4 = (float4*)Xs;
#pragma unroll
    for (int i = 0; i < 8; i++) Xs4[tid + i * 256] = Xg[tid + i * 256];
    __syncthreads();

    const int ty = tid >> 4, tx = tid & 15;
    const float4* W4 = (const float4*)W;

    float acc[4][8];
#pragma unroll
    for (int i = 0; i < 4; i++)
#pragma unroll
        for (int j = 0; j < 8; j++) acc[i][j] = 0.0f;

#pragma unroll 4
    for (int kk = 0; kk < 128; kk++) {
        float4 w0 = __ldg(&W4[kk * 32 + tx]);
        float4 w1 = __ldg(&W4[kk * 32 + tx + 16]);
#pragma unroll
        for (int i = 0; i < 4; i++) {
            float xv = Xs[(4 * ty + i) * 128 + kk];
            acc[i][0] += xv * w0.x; acc[i][1] += xv * w0.y;
            acc[i][2] += xv * w0.z; acc[i][3] += xv * w0.w;
            acc[i][4] += xv * w1.x; acc[i][5] += xv * w1.y;
            acc[i][6] += xv * w1.z; acc[i][7] += xv * w1.w;
        }
    }

    float4 b0 = __ldg(&((const float4*)bias)[tx]);
    float4 b1 = __ldg(&((const float4*)bias)[tx + 16]);
#pragma unroll
    for (int i = 0; i < 4; i++) {
        float4 o0 = make_float4(acc[i][0] + b0.x, acc[i][1] + b0.y,
                                acc[i][2] + b0.z, acc[i][3] + b0.w);
        float4 o1 = make_float4(acc[i][4] + b1.x, acc[i][5] + b1.y,
                                acc[i][6] + b1.z, acc[i][7] + b1.w);
        if (round_out) {
            o0.x = to_tf32(o0.x); o0.y = to_tf32(o0.y);
            o0.z = to_tf32(o0.z); o0.w = to_tf32(o0.w);
            o1.x = to_tf32(o1.x); o1.y = to_tf32(o1.y);
            o1.z = to_tf32(o1.z); o1.w = to_tf32(o1.w);
        }
        float4* yr = (float4*)(Y + (row0 + 4 * ty + i) * Dd);
        yr[tx] = o0;
        yr[tx + 16] = o1;
    }
}

template <bool ROUND>
__global__ __launch_bounds__(256) void proj_kernel(
    const float* __restrict__ X, const float* __restrict__ W,
    const float* __restrict__ bias, float* __restrict__ Y) {
    __shared__ float Xs[64 * 128];
    proj_body(X, W, bias, Y, (size_t)blockIdx.x * 64, ROUND, Xs);
}

// Fused q-proj (no round) + k-proj (round): independent GEMMs, one launch.
__global__ __launch_bounds__(256) void proj_qk_kernel(
    const float* __restrict__ Xq, const float* __restrict__ Wq,
    const float* __restrict__ bq, float* __restrict__ Yq,
    const float* __restrict__ Xk, const float* __restrict__ Wk,
    const float* __restrict__ bk, float* __restrict__ Yk, int nblk) {
    __shared__ float Xs[64 * 128];
    if (blockIdx.x < nblk) {
        proj_body(Xq, Wq, bq, Yq, (size_t)blockIdx.x * 64, false, Xs);
    } else {
        proj_body(Xk, Wk, bk, Yk, (size_t)(blockIdx.x - nblk) * 64, true, Xs);
    }
}

// ---------------------------------------------------------------------------
// Flash attention, tf32 mma.sync m16n8k8.
// BM=128 q-rows per CTA, BN=64 keys/tile, 512 threads (16 warps, 8 pairs).
// K double-buffered (cp.async), V single-buffered (latency hidden by softmax).
// Pair wy = warp>>1 owns rows 16wy..16wy+15; wx = warp&1 splits columns.
// Per tile: 2 CTA syncs + 1 pair barrier.
// ---------------------------------------------------------------------------
#define LDQ 132
#define LDK 132
#define LDV 136
#define LDP 68
#define NT  (Nn / 64)

#define Q_OFF   0
#define K_OFF   (128 * LDQ)                 // 16896
#define KSTAGE  (64 * LDK)                  // 8448
#define V_OFF   (K_OFF + 2 * KSTAGE)        // 33792
#define P_OFF   (V_OFF + 64 * LDV)          // 42496
#define RM_OFF  (P_OFF + 128 * LDP)         // 51200
#define RS_OFF  (RM_OFF + 256)
#define ATTN_SMEM_FLOATS (RS_OFF + 256)     // 51712 floats = 206848 B

__device__ __forceinline__ void cp16(uint32_t dst, const void* src) {
    asm volatile("cp.async.cg.shared.global [%0], [%1], 16;"
                 :: "r"(dst), "l"(src));
}

__device__ __forceinline__ void mma_tf32(float c[4],
                                         unsigned a0, unsigned a1,
                                         unsigned a2, unsigned a3,
                                         unsigned b0, unsigned b1) {
    asm volatile(
        "mma.sync.aligned.m16n8k8.row.col.f32.tf32.tf32.f32 "
        "{%0,%1,%2,%3},{%4,%5,%6,%7},{%8,%9},{%0,%1,%2,%3};\n"
        : "+f"(c[0]), "+f"(c[1]), "+f"(c[2]), "+f"(c[3])
        : "r"(a0), "r"(a1), "r"(a2), "r"(a3), "r"(b0), "r"(b1));
}

__global__ __launch_bounds__(512, 1) void attn_kernel(
    const float* __restrict__ q, const float* __restrict__ k,
    const float* __restrict__ v, const int* __restrict__ mask,
    float* __restrict__ out) {
    extern __shared__ float sm[];
    float* Qs = sm + Q_OFF;
    float* Vs = sm + V_OFF;
    float* Ps = sm + P_OFF;
    float* redm = sm + RM_OFF;
    float* reds = sm + RS_OFF;

    const int tid = threadIdx.x;
    const int lane = tid & 31, warp = tid >> 5;
    const int g = lane >> 2, tg = lane & 3;
    const int wy = warp >> 1, wx = warp & 1;
    const int b = blockIdx.y;
    const int q0 = blockIdx.x * 128;
    const float SCALE = 0.08838834764831845f;  // 1/sqrt(128)

    const uint32_t sm_u32 = (uint32_t)__cvta_generic_to_shared(sm);
    const uint32_t k_u32 = sm_u32 + K_OFF * 4;
    const uint32_t v_u32 = sm_u32 + V_OFF * 4;

    // Load Q tile (128 x 128), pre-scaled, RNA tf32-rounded
    const float4* Qg = (const float4*)(q + ((size_t)b * Nn + q0) * Dd);
#pragma unroll
    for (int i = 0; i < 8; i++) {
        int f = tid + i * 512;
        float4 t = Qg[f];
        t.x = to_tf32(t.x * SCALE); t.y = to_tf32(t.y * SCALE);
        t.z = to_tf32(t.z * SCALE); t.w = to_tf32(t.w * SCALE);
        int r = f >> 5, c = (f & 31) * 4;
        *(float4*)&Qs[r * LDQ + c] = t;
    }

    const int r0 = 16 * wy + g, r1 = r0 + 8;

    float oc[8][4];
#pragma unroll
    for (int nt = 0; nt < 8; nt++)
#pragma unroll
        for (int j = 0; j < 4; j++) oc[nt][j] = 0.0f;

    float m0 = NEGINF, m1 = NEGINF, l0 = 0.0f, l1 = 0.0f;

    const int* mb =
        mask + (size_t)b * MASKN * MASKN + (size_t)(q0 + 1) * MASKN + 1;

    // Prefetch K tile 0 into stage 0
    {
        const float4* Kg = (const float4*)(k + ((size_t)b * Nn) * Dd);
#pragma unroll
        for (int i = 0; i < 4; i++) {
            int f = tid + i * 512;
            int r = f >> 5, c = (f & 31) * 4;
            cp16(k_u32 + (uint32_t)(r * LDK + c) * 4, Kg + f);
        }
        asm volatile("cp.async.commit_group;");
    }

    for (int ti = 0; ti < NT; ti++) {
        const int kt = ti * 64;
        const int cur = ti & 1;
        float* Ksc = sm + K_OFF + cur * KSTAGE;
        const bool hasnext = (ti + 1 < NT);

        // All threads finished previous tile (PV reads of V buffer and of
        // K stage `nxt`); covers Qs stores on ti==0.
        __syncthreads();

        // Issue V(ti) into the single V buffer.
        {
            const float4* Vg =
                (const float4*)(v + ((size_t)b * Nn + kt) * Dd);
#pragma unroll
            for (int i = 0; i < 4; i++) {
                int f = tid + i * 512;
                int r = f >> 5, c = (f & 31) * 4;
                cp16(v_u32 + (uint32_t)(r * LDV + c) * 4, Vg + f);
            }
            asm volatile("cp.async.commit_group;");
        }
        // Issue K(ti+1) into the other stage.
        if (hasnext) {
            const int nxt = cur ^ 1;
            const float4* Kg =
                (const float4*)(k + ((size_t)b * Nn + kt + 64) * Dd);
            uint32_t kb = k_u32 + (uint32_t)(nxt * KSTAGE) * 4;
#pragma unroll
            for (int i = 0; i < 4; i++) {
                int f = tid + i * 512;
                int r = f >> 5, c = (f & 31) * 4;
                cp16(kb + (uint32_t)(r * LDK + c) * 4, Kg + f);
            }
            asm volatile("cp.async.commit_group;");
            asm volatile("cp.async.wait_group 2;" ::: "memory");  // K(ti) done
        } else {
            asm volatile("cp.async.wait_group 1;" ::: "memory");  // K(ti) done
        }
        __syncthreads();  // K(ti) visible CTA-wide

        // ---- Mask prefetch as a 16-bit register bitmask ----
        unsigned mkbits = 0;
#pragma unroll
        for (int nt = 0; nt < 4; nt++) {
            int cb = 32 * wx + 8 * nt + 2 * tg;
            const int* mr0 = mb + (size_t)r0 * MASKN + kt + cb;
            const int* mr1 = mb + (size_t)r1 * MASKN + kt + cb;
            mkbits |= (__ldg(mr0)     ? 1u : 0u) << (4 * nt + 0);
            mkbits |= (__ldg(mr0 + 1) ? 1u : 0u) << (4 * nt + 1);
            mkbits |= (__ldg(mr1)     ? 1u : 0u) << (4 * nt + 2);
            mkbits |= (__ldg(mr1 + 1) ? 1u : 0u) << (4 * nt + 3);
        }

        // ---- S = Q.K^T via tf32 mma ----
        float sc[4][4];
#pragma unroll
        for (int nt = 0; nt < 4; nt++)
#pragma unroll
            for (int j = 0; j < 4; j++) sc[nt][j] = 0.0f;

#pragma unroll
        for (int s = 0; s < 16; s++) {
            int d0 = 8 * s;
            unsigned a0 = __float_as_uint(Qs[r0 * LDQ + d0 + tg]);
            unsigned a1 = __float_as_uint(Qs[r1 * LDQ + d0 + tg]);
            unsigned a2 = __float_as_uint(Qs[r0 * LDQ + d0 + tg + 4]);
            unsigned a3 = __float_as_uint(Qs[r1 * LDQ + d0 + tg + 4]);
#pragma unroll
            for (int nt = 0; nt < 4; nt++) {
                int n = 32 * wx + 8 * nt + g;
                unsigned b0 = __float_as_uint(Ksc[n * LDK + d0 + tg]);
                unsigned b1 = __float_as_uint(Ksc[n * LDK + d0 + tg + 4]);
                mma_tf32(sc[nt], a0, a1, a2, a3, b0, b1);
            }
        }

        // ---- Apply mask ----
#pragma unroll
        for (int nt = 0; nt < 4; nt++) {
            if (mkbits & (1u << (4 * nt + 0))) sc[nt][0] = NEGINF;
            if (mkbits & (1u << (4 * nt + 1))) sc[nt][1] = NEGINF;
            if (mkbits & (1u << (4 * nt + 2))) sc[nt][2] = NEGINF;
            if (mkbits & (1u << (4 * nt + 3))) sc[nt][3] = NEGINF;
        }

        // ---- Row max: quad shfl + pair exchange ----
        float rm0 = NEGINF, rm1 = NEGINF;
#pragma unroll
        for (int nt = 0; nt < 4; nt++) {
            rm0 = fmaxf(rm0, fmaxf(sc[nt][0], sc[nt][1]));
            rm1 = fmaxf(rm1, fmaxf(sc[nt][2], sc[nt][3]));
        }
        rm0 = fmaxf(rm0, __shfl_xor_sync(0xffffffffu, rm0, 1));
        rm0 = fmaxf(rm0, __shfl_xor_sync(0xffffffffu, rm0, 2));
        rm1 = fmaxf(rm1, __shfl_xor_sync(0xffffffffu, rm1, 1));
        rm1 = fmaxf(rm1, __shfl_xor_sync(0xffffffffu, rm1, 2));
        if (tg == 0) {
            redm[wy * 32 + wx * 16 + g] = rm0;
            redm[wy * 32 + wx * 16 + g + 8] = rm1;
        }
        asm volatile("bar.sync %0, %1;" :: "r"(wy + 1), "r"(64) : "memory");

        float tmx0 = fmaxf(redm[wy * 32 + g], redm[wy * 32 + 16 + g]);
        float tmx1 = fmaxf(redm[wy * 32 + g + 8], redm[wy * 32 + 24 + g]);
        float mn0 = fmaxf(m0, tmx0), mn1 = fmaxf(m1, tmx1);
        float corr0 = (mn0 == NEGINF) ? 1.0f : __expf(m0 - mn0);
        float corr1 = (mn1 == NEGINF) ? 1.0f : __expf(m1 - mn1);
        m0 = mn0; m1 = mn1;

        // ---- p = exp(s-m); write P (RNA tf32); partial sums ----
        float ps0 = 0.0f, ps1 = 0.0f;
#pragma unroll
        for (int nt = 0; nt < 4; nt++) {
            float p0 = (m0 == NEGINF) ? 0.0f : __expf(sc[nt][0] - m0);
            float p1 = (m0 == NEGINF) ? 0.0f : __expf(sc[nt][1] - m0);
            float p2 = (m1 == NEGINF) ? 0.0f : __expf(sc[nt][2] - m1);
            float p3 = (m1 == NEGINF) ? 0.0f : __expf(sc[nt][3] - m1);
            ps0 += p0 + p1;
            ps1 += p2 + p3;
            int col = 32 * wx + 8 * nt + 2 * tg;
            *(float2*)&Ps[r0 * LDP + col] = make_float2(to_tf32(p0), to_tf32(p1));
            *(float2*)&Ps[r1 * LDP + col] = make_float2(to_tf32(p2), to_tf32(p3));
        }
        ps0 += __shfl_xor_sync(0xffffffffu, ps0, 1);
        ps0 += __shfl_xor_sync(0xffffffffu, ps0, 2);
        ps1 += __shfl_xor_sync(0xffffffffu, ps1, 1);
        ps1 += __shfl_xor_sync(0xffffffffu, ps1, 2);
        if (tg == 0) {
            reds[wy * 32 + wx * 16 + g] = ps0;
            reds[wy * 32 + wx * 16 + g + 8] = ps1;
        }

        // Wait for V(ti); CTA sync also publishes Ps and reds.
        if (hasnext) {
            asm volatile("cp.async.wait_group 1;" ::: "memory");
        } else {
            asm volatile("cp.async.wait_group 0;" ::: "memory");
        }
        __syncthreads();

        l0 = l0 * corr0 + reds[wy * 32 + g] + reds[wy * 32 + 16 + g];
        l1 = l1 * corr1 + reds[wy * 32 + g + 8] + reds[wy * 32 + 24 + g];

        // ---- Rescale O; O += P.V via tf32 mma ----
#pragma unroll
        for (int nt = 0; nt < 8; nt++) {
            oc[nt][0] *= corr0; oc[nt][1] *= corr0;
            oc[nt][2] *= corr1; oc[nt][3] *= corr1;
        }
#pragma unroll
        for (int s = 0; s < 8; s++) {
            int k0 = 8 * s;
            unsigned a0 = __float_as_uint(Ps[r0 * LDP + k0 + tg]);
            unsigned a1 = __float_as_uint(Ps[r1 * LDP + k0 + tg]);
            unsigned a2 = __float_as_uint(Ps[r0 * LDP + k0 + tg + 4]);
            unsigned a3 = __float_as_uint(Ps[r1 * LDP + k0 + tg + 4]);
#pragma unroll
            for (int nt = 0; nt < 8; nt++) {
                int n = 64 * wx + 8 * nt + g;
                unsigned b0 = __float_as_uint(Vs[(k0 + tg) * LDV + n]);
                unsigned b1 = __float_as_uint(Vs[(k0 + tg + 4) * LDV + n]);
                mma_tf32(oc[nt], a0, a1, a2, a3, b0, b1);
            }
        }
    }

    // ---- Epilogue: out = O / l (l==0 -> 0, matches NaN->0 semantics) ----
    float i0 = (l0 > 0.0f) ? 1.0f / l0 : 0.0f;
    float i1 = (l1 > 0.0f) ? 1.0f / l1 : 0.0f;
    float* ob = out + ((size_t)b * Nn + q0) * Dd;
#pragma unroll
    for (int nt = 0; nt < 8; nt++) {
        int col = 64 * wx + 8 * nt + 2 * tg;
        *(float2*)&ob[(size_t)r0 * Dd + col] =
            make_float2(oc[nt][0] * i0, oc[nt][1] * i0);
        *(float2*)&ob[(size_t)r1 * Dd + col] =
            make_float2(oc[nt][2] * i1, oc[nt][3] * i1);
    }
}

// ---------------------------------------------------------------------------
// Launch: fused q+k projections -> v projection -> attention -> out projection.
// ---------------------------------------------------------------------------
extern "C" void kernel_launch(void* const* d_in, const int* in_sizes, int n_in,
                              void* d_out, int out_size) {
    const float* query = (const float*)d_in[0];
    const float* key_  = (const float*)d_in[1];
    const int*   mask  = (const int*)d_in[2];
    const float* Wq = (const float*)d_in[3];
    const float* bq = (const float*)d_in[4];
    const float* Wk = (const float*)d_in[5];
    const float* bk = (const float*)d_in[6];
    const float* Wv = (const float*)d_in[7];
    const float* bv = (const float*)d_in[8];
    const float* Wo = (const float*)d_in[9];
    const float* bo = (const float*)d_in[10];
    float* out = (float*)d_out;

    float *qb, *kb, *vb, *ab;
    cudaGetSymbolAddress((void**)&qb, g_q);
    cudaGetSymbolAddress((void**)&kb, g_k);
    cudaGetSymbolAddress((void**)&vb, g_v);
    cudaGetSymbolAddress((void**)&ab, g_ao);

    const int nblk = MROWS / 64;  // 512

    proj_qk_kernel<<<2 * nblk, 256>>>(query, Wq, bq, qb,
                                      key_, Wk, bk, kb, nblk);
    proj_kernel<true><<<nblk, 256>>>(kb, Wv, bv, vb);  // v = k_proj @ Wv + bv

    size_t smem_bytes = (size_t)ATTN_SMEM_FLOATS * sizeof(float);
    cudaFuncSetAttribute(attn_kernel, cudaFuncAttributeMaxDynamicSharedMemorySize,
                         (int)smem_bytes);
    attn_kernel<<<dim3(Nn / 128, Bb), 512, smem_bytes>>>(qb, kb, vb, mask, ab);

    proj_kernel<false><<<nblk, 256>>>(ab, Wo, bo, out);
}

// round 8
// speedup vs baseline: 3.6338x; 1.2015x over previous
#include <cuda_runtime.h>
#include <cstdint>

// Problem constants
#define Bb 16
#define Nn 2048
#define Dd 128
#define MASKN 2049
#define MROWS (Bb * Nn)

#define NEGINF __int_as_float(0xff800000)

// Scratch (allocation-free rule: __device__ globals)
__device__ float g_q[MROWS * Dd];
__device__ float g_k[MROWS * Dd];
__device__ float g_v[MROWS * Dd];
__device__ float g_ao[MROWS * Dd];

__device__ __forceinline__ float to_tf32(float x) {
    float y;
    asm("cvt.rna.tf32.f32 %0, %1;" : "=f"(y) : "f"(x));
    return y;
}

__device__ __forceinline__ void cp16(uint32_t dst, const void* src) {
    asm volatile("cp.async.cg.shared.global [%0], [%1], 16;"
                 :: "r"(dst), "l"(src));
}

__device__ __forceinline__ void mma_tf32(float c[4],
                                         unsigned a0, unsigned a1,
                                         unsigned a2, unsigned a3,
                                         unsigned b0, unsigned b1) {
    asm volatile(
        "mma.sync.aligned.m16n8k8.row.col.f32.tf32.tf32.f32 "
        "{%0,%1,%2,%3},{%4,%5,%6,%7},{%8,%9},{%0,%1,%2,%3};\n"
        : "+f"(c[0]), "+f"(c[1]), "+f"(c[2]), "+f"(c[3])
        : "r"(a0), "r"(a1), "r"(a2), "r"(a3), "r"(b0), "r"(b1));
}

// ---------------------------------------------------------------------------
// tf32-MMA projection: Y[64 rows, 128] = X @ W + bias.
// 256 threads / 8 warps: warp (wy=w>>1, wx=w&1) -> rows 16wy..+15, cols 64wx..+63.
// X, W cp.async'd to smem, then RNA-rounded in place (avoids truncation bias).
// Pads: LDX=132 (A frag: bank 4g+tg), LDW=136 (B frag: bank 8tg+g).
// ---------------------------------------------------------------------------
#define LDX 132
#define LDW 136
#define PROJ_SMEM_FLOATS (64 * LDX + 128 * LDW)   // 25856 floats = 103424 B

__device__ __forceinline__ void proj_mma_body(
    const float* __restrict__ X, const float* __restrict__ W,
    const float* __restrict__ bias, float* __restrict__ Y,
    size_t row0, bool round_out, float* sm) {
    float* Xs = sm;
    float* Ws = sm + 64 * LDX;

    const int tid = threadIdx.x;
    const int lane = tid & 31, warp = tid >> 5;
    const int g = lane >> 2, tg = lane & 3;
    const int wy = warp >> 1, wx = warp & 1;

    const uint32_t xs_u32 = (uint32_t)__cvta_generic_to_shared(Xs);
    const uint32_t ws_u32 = (uint32_t)__cvta_generic_to_shared(Ws);

    // cp.async X (64x128) and W (128x128)
    const float4* Xg = (const float4*)(X + row0 * Dd);
#pragma unroll
    for (int i = 0; i < 8; i++) {
        int f = tid + i * 256;
        int r = f >> 5, c = (f & 31) * 4;
        cp16(xs_u32 + (uint32_t)(r * LDX + c) * 4, Xg + f);
    }
    const float4* Wg = (const float4*)W;
#pragma unroll
    for (int i = 0; i < 16; i++) {
        int f = tid + i * 256;
        int r = f >> 5, c = (f & 31) * 4;
        cp16(ws_u32 + (uint32_t)(r * LDW + c) * 4, Wg + f);
    }
    asm volatile("cp.async.commit_group;");
    asm volatile("cp.async.wait_group 0;" ::: "memory");
    __syncthreads();

    // RNA-round X and W in place (each thread rounds what it loaded)
#pragma unroll
    for (int i = 0; i < 8; i++) {
        int f = tid + i * 256;
        int r = f >> 5, c = (f & 31) * 4;
        float4* p = (float4*)&Xs[r * LDX + c];
        float4 t = *p;
        t.x = to_tf32(t.x); t.y = to_tf32(t.y);
        t.z = to_tf32(t.z); t.w = to_tf32(t.w);
        *p = t;
    }
#pragma unroll
    for (int i = 0; i < 16; i++) {
        int f = tid + i * 256;
        int r = f >> 5, c = (f & 31) * 4;
        float4* p = (float4*)&Ws[r * LDW + c];
        float4 t = *p;
        t.x = to_tf32(t.x); t.y = to_tf32(t.y);
        t.z = to_tf32(t.z); t.w = to_tf32(t.w);
        *p = t;
    }
    __syncthreads();

    const int r0 = 16 * wy + g, r1 = r0 + 8;

    float oc[8][4];
#pragma unroll
    for (int nt = 0; nt < 8; nt++)
#pragma unroll
        for (int j = 0; j < 4; j++) oc[nt][j] = 0.0f;

#pragma unroll
    for (int s = 0; s < 16; s++) {
        int d0 = 8 * s;
        unsigned a0 = __float_as_uint(Xs[r0 * LDX + d0 + tg]);
        unsigned a1 = __float_as_uint(Xs[r1 * LDX + d0 + tg]);
        unsigned a2 = __float_as_uint(Xs[r0 * LDX + d0 + tg + 4]);
        unsigned a3 = __float_as_uint(Xs[r1 * LDX + d0 + tg + 4]);
#pragma unroll
        for (int nt = 0; nt < 8; nt++) {
            int n = 64 * wx + 8 * nt + g;
            unsigned b0 = __float_as_uint(Ws[(d0 + tg) * LDW + n]);
            unsigned b1 = __float_as_uint(Ws[(d0 + tg + 4) * LDW + n]);
            mma_tf32(oc[nt], a0, a1, a2, a3, b0, b1);
        }
    }

    // Epilogue: add bias, optional RNA-tf32 rounding, store float2 pairs
    float* yr0 = Y + (row0 + r0) * Dd;
    float* yr1 = Y + (row0 + r1) * Dd;
#pragma unroll
    for (int nt = 0; nt < 8; nt++) {
        int col = 64 * wx + 8 * nt + 2 * tg;
        float2 bv = __ldg((const float2*)(bias + col));
        float2 o0 = make_float2(oc[nt][0] + bv.x, oc[nt][1] + bv.y);
        float2 o1 = make_float2(oc[nt][2] + bv.x, oc[nt][3] + bv.y);
        if (round_out) {
            o0.x = to_tf32(o0.x); o0.y = to_tf32(o0.y);
            o1.x = to_tf32(o1.x); o1.y = to_tf32(o1.y);
        }
        *(float2*)&yr0[col] = o0;
        *(float2*)&yr1[col] = o1;
    }
}

template <bool ROUND>
__global__ __launch_bounds__(256, 2) void proj_kernel(
    const float* __restrict__ X, const float* __restrict__ W,
    const float* __restrict__ bias, float* __restrict__ Y) {
    extern __shared__ float psm[];
    proj_mma_body(X, W, bias, Y, (size_t)blockIdx.x * 64, ROUND, psm);
}

// Fused q-proj (no round) + k-proj (round): independent GEMMs, one launch.
__global__ __launch_bounds__(256, 2) void proj_qk_kernel(
    const float* __restrict__ Xq, const float* __restrict__ Wq,
    const float* __restrict__ bq, float* __restrict__ Yq,
    const float* __restrict__ Xk, const float* __restrict__ Wk,
    const float* __restrict__ bk, float* __restrict__ Yk, int nblk) {
    extern __shared__ float psm[];
    if (blockIdx.x < nblk) {
        proj_mma_body(Xq, Wq, bq, Yq, (size_t)blockIdx.x * 64, false, psm);
    } else {
        proj_mma_body(Xk, Wk, bk, Yk, (size_t)(blockIdx.x - nblk) * 64, true, psm);
    }
}

// ---------------------------------------------------------------------------
// Flash attention, tf32 mma.sync m16n8k8 (unchanged from round 7).
// BM=128 q-rows per CTA, BN=64 keys/tile, 512 threads (16 warps, 8 pairs).
// K double-buffered (cp.async), V single-buffered.
// ---------------------------------------------------------------------------
#define LDQ 132
#define LDK 132
#define LDV 136
#define LDP 68
#define NT  (Nn / 64)

#define Q_OFF   0
#define K_OFF   (128 * LDQ)                 // 16896
#define KSTAGE  (64 * LDK)                  // 8448
#define V_OFF   (K_OFF + 2 * KSTAGE)        // 33792
#define P_OFF   (V_OFF + 64 * LDV)          // 42496
#define RM_OFF  (P_OFF + 128 * LDP)         // 51200
#define RS_OFF  (RM_OFF + 256)
#define ATTN_SMEM_FLOATS (RS_OFF + 256)     // 51712 floats = 206848 B

__global__ __launch_bounds__(512, 1) void attn_kernel(
    const float* __restrict__ q, const float* __restrict__ k,
    const float* __restrict__ v, const int* __restrict__ mask,
    float* __restrict__ out) {
    extern __shared__ float sm[];
    float* Qs = sm + Q_OFF;
    float* Vs = sm + V_OFF;
    float* Ps = sm + P_OFF;
    float* redm = sm + RM_OFF;
    float* reds = sm + RS_OFF;

    const int tid = threadIdx.x;
    const int lane = tid & 31, warp = tid >> 5;
    const int g = lane >> 2, tg = lane & 3;
    const int wy = warp >> 1, wx = warp & 1;
    const int b = blockIdx.y;
    const int q0 = blockIdx.x * 128;
    const float SCALE = 0.08838834764831845f;  // 1/sqrt(128)

    const uint32_t sm_u32 = (uint32_t)__cvta_generic_to_shared(sm);
    const uint32_t k_u32 = sm_u32 + K_OFF * 4;
    const uint32_t v_u32 = sm_u32 + V_OFF * 4;

    // Load Q tile (128 x 128), pre-scaled, RNA tf32-rounded
    const float4* Qg = (const float4*)(q + ((size_t)b * Nn + q0) * Dd);
#pragma unroll
    for (int i = 0; i < 8; i++) {
        int f = tid + i * 512;
        float4 t = Qg[f];
        t.x = to_tf32(t.x * SCALE); t.y = to_tf32(t.y * SCALE);
        t.z = to_tf32(t.z * SCALE); t.w = to_tf32(t.w * SCALE);
        int r = f >> 5, c = (f & 31) * 4;
        *(float4*)&Qs[r * LDQ + c] = t;
    }

    const int r0 = 16 * wy + g, r1 = r0 + 8;

    float oc[8][4];
#pragma unroll
    for (int nt = 0; nt < 8; nt++)
#pragma unroll
        for (int j = 0; j < 4; j++) oc[nt][j] = 0.0f;

    float m0 = NEGINF, m1 = NEGINF, l0 = 0.0f, l1 = 0.0f;

    const int* mb =
        mask + (size_t)b * MASKN * MASKN + (size_t)(q0 + 1) * MASKN + 1;

    // Prefetch K tile 0 into stage 0
    {
        const float4* Kg = (const float4*)(k + ((size_t)b * Nn) * Dd);
#pragma unroll
        for (int i = 0; i < 4; i++) {
            int f = tid + i * 512;
            int r = f >> 5, c = (f & 31) * 4;
            cp16(k_u32 + (uint32_t)(r * LDK + c) * 4, Kg + f);
        }
        asm volatile("cp.async.commit_group;");
    }

    for (int ti = 0; ti < NT; ti++) {
        const int kt = ti * 64;
        const int cur = ti & 1;
        float* Ksc = sm + K_OFF + cur * KSTAGE;
        const bool hasnext = (ti + 1 < NT);

        // All threads finished previous tile (PV reads of V buffer and of
        // K stage `nxt`); covers Qs stores on ti==0.
        __syncthreads();

        // Issue V(ti) into the single V buffer.
        {
            const float4* Vg =
                (const float4*)(v + ((size_t)b * Nn + kt) * Dd);
#pragma unroll
            for (int i = 0; i < 4; i++) {
                int f = tid + i * 512;
                int r = f >> 5, c = (f & 31) * 4;
                cp16(v_u32 + (uint32_t)(r * LDV + c) * 4, Vg + f);
            }
            asm volatile("cp.async.commit_group;");
        }
        // Issue K(ti+1) into the other stage.
        if (hasnext) {
            const int nxt = cur ^ 1;
            const float4* Kg =
                (const float4*)(k + ((size_t)b * Nn + kt + 64) * Dd);
            uint32_t kb = k_u32 + (uint32_t)(nxt * KSTAGE) * 4;
#pragma unroll
            for (int i = 0; i < 4; i++) {
                int f = tid + i * 512;
                int r = f >> 5, c = (f & 31) * 4;
                cp16(kb + (uint32_t)(r * LDK + c) * 4, Kg + f);
            }
            asm volatile("cp.async.commit_group;");
            asm volatile("cp.async.wait_group 2;" ::: "memory");  // K(ti) done
        } else {
            asm volatile("cp.async.wait_group 1;" ::: "memory");  // K(ti) done
        }
        __syncthreads();  // K(ti) visible CTA-wide

        // ---- Mask prefetch as a 16-bit register bitmask ----
        unsigned mkbits = 0;
#pragma unroll
        for (int nt = 0; nt < 4; nt++) {
            int cb = 32 * wx + 8 * nt + 2 * tg;
            const int* mr0 = mb + (size_t)r0 * MASKN + kt + cb;
            const int* mr1 = mb + (size_t)r1 * MASKN + kt + cb;
            mkbits |= (__ldg(mr0)     ? 1u : 0u) << (4 * nt + 0);
            mkbits |= (__ldg(mr0 + 1) ? 1u : 0u) << (4 * nt + 1);
            mkbits |= (__ldg(mr1)     ? 1u : 0u) << (4 * nt + 2);
            mkbits |= (__ldg(mr1 + 1) ? 1u : 0u) << (4 * nt + 3);
        }

        // ---- S = Q.K^T via tf32 mma ----
        float sc[4][4];
#pragma unroll
        for (int nt = 0; nt < 4; nt++)
#pragma unroll
            for (int j = 0; j < 4; j++) sc[nt][j] = 0.0f;

#pragma unroll
        for (int s = 0; s < 16; s++) {
            int d0 = 8 * s;
            unsigned a0 = __float_as_uint(Qs[r0 * LDQ + d0 + tg]);
            unsigned a1 = __float_as_uint(Qs[r1 * LDQ + d0 + tg]);
            unsigned a2 = __float_as_uint(Qs[r0 * LDQ + d0 + tg + 4]);
            unsigned a3 = __float_as_uint(Qs[r1 * LDQ + d0 + tg + 4]);
#pragma unroll
            for (int nt = 0; nt < 4; nt++) {
                int n = 32 * wx + 8 * nt + g;
                unsigned b0 = __float_as_uint(Ksc[n * LDK + d0 + tg]);
                unsigned b1 = __float_as_uint(Ksc[n * LDK + d0 + tg + 4]);
                mma_tf32(sc[nt], a0, a1, a2, a3, b0, b1);
            }
        }

        // ---- Apply mask ----
#pragma unroll
        for (int nt = 0; nt < 4; nt++) {
            if (mkbits & (1u << (4 * nt + 0))) sc[nt][0] = NEGINF;
            if (mkbits & (1u << (4 * nt + 1))) sc[nt][1] = NEGINF;
            if (mkbits & (1u << (4 * nt + 2))) sc[nt][2] = NEGINF;
            if (mkbits & (1u << (4 * nt + 3))) sc[nt][3] = NEGINF;
        }

        // ---- Row max: quad shfl + pair exchange ----
        float rm0 = NEGINF, rm1 = NEGINF;
#pragma unroll
        for (int nt = 0; nt < 4; nt++) {
            rm0 = fmaxf(rm0, fmaxf(sc[nt][0], sc[nt][1]));
            rm1 = fmaxf(rm1, fmaxf(sc[nt][2], sc[nt][3]));
        }
        rm0 = fmaxf(rm0, __shfl_xor_sync(0xffffffffu, rm0, 1));
        rm0 = fmaxf(rm0, __shfl_xor_sync(0xffffffffu, rm0, 2));
        rm1 = fmaxf(rm1, __shfl_xor_sync(0xffffffffu, rm1, 1));
        rm1 = fmaxf(rm1, __shfl_xor_sync(0xffffffffu, rm1, 2));
        if (tg == 0) {
            redm[wy * 32 + wx * 16 + g] = rm0;
            redm[wy * 32 + wx * 16 + g + 8] = rm1;
        }
        asm volatile("bar.sync %0, %1;" :: "r"(wy + 1), "r"(64) : "memory");

        float tmx0 = fmaxf(redm[wy * 32 + g], redm[wy * 32 + 16 + g]);
        float tmx1 = fmaxf(redm[wy * 32 + g + 8], redm[wy * 32 + 24 + g]);
        float mn0 = fmaxf(m0, tmx0), mn1 = fmaxf(m1, tmx1);
        float corr0 = (mn0 == NEGINF) ? 1.0f : __expf(m0 - mn0);
        float corr1 = (mn1 == NEGINF) ? 1.0f : __expf(m1 - mn1);
        m0 = mn0; m1 = mn1;

        // ---- p = exp(s-m); write P (RNA tf32); partial sums ----
        float ps0 = 0.0f, ps1 = 0.0f;
#pragma unroll
        for (int nt = 0; nt < 4; nt++) {
            float p0 = (m0 == NEGINF) ? 0.0f : __expf(sc[nt][0] - m0);
            float p1 = (m0 == NEGINF) ? 0.0f : __expf(sc[nt][1] - m0);
            float p2 = (m1 == NEGINF) ? 0.0f : __expf(sc[nt][2] - m1);
            float p3 = (m1 == NEGINF) ? 0.0f : __expf(sc[nt][3] - m1);
            ps0 += p0 + p1;
            ps1 += p2 + p3;
            int col = 32 * wx + 8 * nt + 2 * tg;
            *(float2*)&Ps[r0 * LDP + col] = make_float2(to_tf32(p0), to_tf32(p1));
            *(float2*)&Ps[r1 * LDP + col] = make_float2(to_tf32(p2), to_tf32(p3));
        }
        ps0 += __shfl_xor_sync(0xffffffffu, ps0, 1);
        ps0 += __shfl_xor_sync(0xffffffffu, ps0, 2);
        ps1 += __shfl_xor_sync(0xffffffffu, ps1, 1);
        ps1 += __shfl_xor_sync(0xffffffffu, ps1, 2);
        if (tg == 0) {
            reds[wy * 32 + wx * 16 + g] = ps0;
            reds[wy * 32 + wx * 16 + g + 8] = ps1;
        }

        // Wait for V(ti); CTA sync also publishes Ps and reds.
        if (hasnext) {
            asm volatile("cp.async.wait_group 1;" ::: "memory");
        } else {
            asm volatile("cp.async.wait_group 0;" ::: "memory");
        }
        __syncthreads();

        l0 = l0 * corr0 + reds[wy * 32 + g] + reds[wy * 32 + 16 + g];
        l1 = l1 * corr1 + reds[wy * 32 + g + 8] + reds[wy * 32 + 24 + g];

        // ---- Rescale O; O += P.V via tf32 mma ----
#pragma unroll
        for (int nt = 0; nt < 8; nt++) {
            oc[nt][0] *= corr0; oc[nt][1] *= corr0;
            oc[nt][2] *= corr1; oc[nt][3] *= corr1;
        }
#pragma unroll
        for (int s = 0; s < 8; s++) {
            int k0 = 8 * s;
            unsigned a0 = __float_as_uint(Ps[r0 * LDP + k0 + tg]);
            unsigned a1 = __float_as_uint(Ps[r1 * LDP + k0 + tg]);
            unsigned a2 = __float_as_uint(Ps[r0 * LDP + k0 + tg + 4]);
            unsigned a3 = __float_as_uint(Ps[r1 * LDP + k0 + tg + 4]);
#pragma unroll
            for (int nt = 0; nt < 8; nt++) {
                int n = 64 * wx + 8 * nt + g;
                unsigned b0 = __float_as_uint(Vs[(k0 + tg) * LDV + n]);
                unsigned b1 = __float_as_uint(Vs[(k0 + tg + 4) * LDV + n]);
                mma_tf32(oc[nt], a0, a1, a2, a3, b0, b1);
            }
        }
    }

    // ---- Epilogue: out = O / l (l==0 -> 0, matches NaN->0 semantics) ----
    float i0 = (l0 > 0.0f) ? 1.0f / l0 : 0.0f;
    float i1 = (l1 > 0.0f) ? 1.0f / l1 : 0.0f;
    float* ob = out + ((size_t)b * Nn + q0) * Dd;
#pragma unroll
    for (int nt = 0; nt < 8; nt++) {
        int col = 64 * wx + 8 * nt + 2 * tg;
        *(float2*)&ob[(size_t)r0 * Dd + col] =
            make_float2(oc[nt][0] * i0, oc[nt][1] * i0);
        *(float2*)&ob[(size_t)r1 * Dd + col] =
            make_float2(oc[nt][2] * i1, oc[nt][3] * i1);
    }
}

// ---------------------------------------------------------------------------
// Launch: fused q+k projections -> v projection -> attention -> out projection.
// All projections now run on the tensor pipe (tf32 MMA, RNA-rounded operands).
// ---------------------------------------------------------------------------
extern "C" void kernel_launch(void* const* d_in, const int* in_sizes, int n_in,
                              void* d_out, int out_size) {
    const float* query = (const float*)d_in[0];
    const float* key_  = (const float*)d_in[1];
    const int*   mask  = (const int*)d_in[2];
    const float* Wq = (const float*)d_in[3];
    const float* bq = (const float*)d_in[4];
    const float* Wk = (const float*)d_in[5];
    const float* bk = (const float*)d_in[6];
    const float* Wv = (const float*)d_in[7];
    const float* bv = (const float*)d_in[8];
    const float* Wo = (const float*)d_in[9];
    const float* bo = (const float*)d_in[10];
    float* out = (float*)d_out;

    float *qb, *kb, *vb, *ab;
    cudaGetSymbolAddress((void**)&qb, g_q);
    cudaGetSymbolAddress((void**)&kb, g_k);
    cudaGetSymbolAddress((void**)&vb, g_v);
    cudaGetSymbolAddress((void**)&ab, g_ao);

    const int nblk = MROWS / 64;  // 512
    size_t proj_smem = (size_t)PROJ_SMEM_FLOATS * sizeof(float);  // 103424 B

    cudaFuncSetAttribute(proj_qk_kernel,
                         cudaFuncAttributeMaxDynamicSharedMemorySize,
                         (int)proj_smem);
    cudaFuncSetAttribute(proj_kernel<true>,
                         cudaFuncAttributeMaxDynamicSharedMemorySize,
                         (int)proj_smem);
    cudaFuncSetAttribute(proj_kernel<false>,
                         cudaFuncAttributeMaxDynamicSharedMemorySize,
                         (int)proj_smem);

    proj_qk_kernel<<<2 * nblk, 256, proj_smem>>>(query, Wq, bq, qb,
                                                 key_, Wk, bk, kb, nblk);
    proj_kernel<true><<<nblk, 256, proj_smem>>>(kb, Wv, bv, vb);

    size_t smem_bytes = (size_t)ATTN_SMEM_FLOATS * sizeof(float);
    cudaFuncSetAttribute(attn_kernel, cudaFuncAttributeMaxDynamicSharedMemorySize,
                         (int)smem_bytes);
    attn_kernel<<<dim3(Nn / 128, Bb), 512, smem_bytes>>>(qb, kb, vb, mask, ab);

    proj_kernel<false><<<nblk, 256, proj_smem>>>(ab, Wo, bo, out);
}